// round 6
// baseline (speedup 1.0000x reference)
#include <cuda_runtime.h>
#include <cuda_fp16.h>
#include <cstdint>

// GPTQ int4 linear on GB300 via legacy tensor path (mma.sync, base sm_103 target):
//   Pass 1 (fused): dequant qweight -> fp16 W[N,K]; convert x -> fp16.
//   Pass 2: 256x128x64 tiled fp16 GEMM, warp tile 64x64, mma.sync.m16n8k16,
//           ldmatrix with fragment double-buffering, 3-stage cp.async pipeline.
// M=8192, N=11008, K=4096, GS=128.

#define M_DIM 8192
#define N_DIM 11008
#define K_DIM 4096
#define BM 256
#define BN 128
#define BK 64                 // halfs per stage (128 bytes per row, SW128)
#define STAGES 3
#define NITER (K_DIM / BK)    // 64
#define THREADS 256

__device__ __half g_Wh[(size_t)N_DIM * K_DIM];   // 90 MB
__device__ __half g_Xh[(size_t)M_DIM * K_DIM];   // 64 MB

#define SWZ128(o) ((o) ^ (((o) >> 3) & 0x70))

#define CP_ASYNC16(dst, src) \
    asm volatile("cp.async.cg.shared.global [%0], [%1], 16;" :: "r"(dst), "l"(src))
#define CP_COMMIT() asm volatile("cp.async.commit_group;" ::: "memory")
#define CP_WAIT(n)  asm volatile("cp.async.wait_group %0;" :: "n"(n) : "memory")

__device__ __forceinline__ uint32_t smem_u32(const void* p) {
    uint32_t a;
    asm("{ .reg .u64 t; cvta.to.shared.u64 t, %1; cvt.u32.u64 %0, t; }" : "=r"(a) : "l"(p));
    return a;
}
__device__ __forceinline__ void ldsm_x4(uint32_t* r, uint32_t addr) {
    asm volatile("ldmatrix.sync.aligned.m8n8.x4.shared.b16 {%0,%1,%2,%3}, [%4];"
                 : "=r"(r[0]), "=r"(r[1]), "=r"(r[2]), "=r"(r[3]) : "r"(addr));
}
__device__ __forceinline__ void mma16816(float* c, const uint32_t* a, uint32_t b0, uint32_t b1) {
    asm volatile("mma.sync.aligned.m16n8k16.row.col.f32.f16.f16.f32 "
                 "{%0,%1,%2,%3}, {%4,%5,%6,%7}, {%8,%9}, {%0,%1,%2,%3};"
                 : "+f"(c[0]), "+f"(c[1]), "+f"(c[2]), "+f"(c[3])
                 : "r"(a[0]), "r"(a[1]), "r"(a[2]), "r"(a[3]), "r"(b0), "r"(b1));
}

// ---------------- Pass 1 (fused): dequant W -> fp16 ; convert x -> fp16 ----------------
#define W_JOBS ((size_t)N_DIM * (K_DIM / 8))     // 5,636,096
#define X_JOBS ((size_t)M_DIM * (K_DIM / 8))     // 4,194,304

__global__ void prologue_kernel(const int* __restrict__ qw,        // [N, K/2], one byte per int32
                                const float* __restrict__ scales,  // [N, 32]
                                const float* __restrict__ zeros,   // [N, 32]
                                const float* __restrict__ x)       // [M, K]
{
    size_t t = (size_t)blockIdx.x * blockDim.x + threadIdx.x;
    if (t < W_JOBS) {
        int n  = (int)(t >> 9);           // K/8 = 512 per row
        int c4 = (int)(t & 511);
        int g  = c4 >> 4;                 // (c4*8)/128
        float sc = scales[(size_t)n * 32 + g];
        float zp = zeros [(size_t)n * 32 + g];
        int4 q = *reinterpret_cast<const int4*>(qw + (size_t)n * 2048 + c4 * 4);
        int qs[4] = {q.x, q.y, q.z, q.w};
        __half h[8];
        #pragma unroll
        for (int j = 0; j < 4; j++) {
            float lo = (float)(qs[j] & 15);
            float hi = (float)((qs[j] >> 4) & 15);
            h[2 * j    ] = __float2half_rn((lo - zp) * sc);
            h[2 * j + 1] = __float2half_rn((hi - zp) * sc);
        }
        *reinterpret_cast<uint4*>(&g_Wh[(size_t)n * K_DIM + (size_t)c4 * 8]) =
            *reinterpret_cast<const uint4*>(h);
    } else if (t - W_JOBS < X_JOBS) {
        size_t base = (t - W_JOBS) * 8;
        float4 a = *reinterpret_cast<const float4*>(x + base);
        float4 b = *reinterpret_cast<const float4*>(x + base + 4);
        __half h[8] = {__float2half_rn(a.x), __float2half_rn(a.y), __float2half_rn(a.z), __float2half_rn(a.w),
                       __float2half_rn(b.x), __float2half_rn(b.y), __float2half_rn(b.z), __float2half_rn(b.w)};
        *reinterpret_cast<uint4*>(&g_Xh[base]) = *reinterpret_cast<const uint4*>(h);
    }
}

// ---------------- Pass 2: mma.sync fp16 GEMM ----------------
// SMEM per stage: A 256x64 fp16 (32KB) + B 128x64 fp16 (16KB) = 48KB. 3 stages = 144KB.
#define A_BYTES 32768
#define STAGE_BYTES 49152
#define SMEM_TOTAL (STAGES * STAGE_BYTES)

__device__ __forceinline__ void load_stage(uint32_t sA, uint32_t sB,
                                           int bm, int bn, int k0, int tid)
{
    #pragma unroll
    for (int j = 0; j < 8; j++) {
        int chunk = tid + j * THREADS;
        int row = chunk >> 3, c16 = chunk & 7;
        uint32_t off = SWZ128((uint32_t)(row * 128 + c16 * 16));
        CP_ASYNC16(sA + off, g_Xh + (size_t)(bm + row) * K_DIM + k0 + c16 * 8);
    }
    #pragma unroll
    for (int j = 0; j < 4; j++) {
        int chunk = tid + j * THREADS;
        int row = chunk >> 3, c16 = chunk & 7;
        uint32_t off = SWZ128((uint32_t)(row * 128 + c16 * 16));
        CP_ASYNC16(sB + off, g_Wh + (size_t)(bn + row) * K_DIM + k0 + c16 * 8);
    }
}

__global__ __launch_bounds__(THREADS, 1)
void gemm_f16_kernel(const float* __restrict__ bias, float* __restrict__ out)
{
    extern __shared__ char smem[];
    const uint32_t sb = smem_u32(smem);
    const int tid = threadIdx.x;
    const int wid = tid >> 5, lane = tid & 31;
    const int warp_m = wid & 3;    // 0..3, 64 rows each
    const int warp_n = wid >> 2;   // 0..1, 64 cols each
    const int bn = blockIdx.x * BN;
    const int bm = blockIdx.y * BM;

    uint32_t sA[STAGES], sB[STAGES];
    #pragma unroll
    for (int s = 0; s < STAGES; s++) {
        sA[s] = sb + s * STAGE_BYTES;
        sB[s] = sA[s] + A_BYTES;
    }

    float acc[4][8][4];   // warp tile 64x64: [m16 tile][n8 tile][reg]
    #pragma unroll
    for (int a = 0; a < 4; a++)
        #pragma unroll
        for (int b = 0; b < 8; b++)
            #pragma unroll
            for (int c = 0; c < 4; c++)
                acc[a][b][c] = 0.0f;

    #pragma unroll
    for (int s = 0; s < STAGES - 1; s++) {
        load_stage(sA[s], sB[s], bm, bn, s * BK, tid);
        CP_COMMIT();
    }

    const int kch_lane = lane >> 4;        // 0/1: k-chunk selector within ldmatrix.x4
    const int row_lane = lane & 15;
    // Per-warp fragment smem byte offsets (row part), col part varies with ks.
    const uint32_t a_row_off[4] = {
        (uint32_t)((warp_m * 64 +  0 + row_lane) * 128),
        (uint32_t)((warp_m * 64 + 16 + row_lane) * 128),
        (uint32_t)((warp_m * 64 + 32 + row_lane) * 128),
        (uint32_t)((warp_m * 64 + 48 + row_lane) * 128)};
    const uint32_t b_row_off[4] = {
        (uint32_t)((warp_n * 64 +  0 + row_lane) * 128),
        (uint32_t)((warp_n * 64 + 16 + row_lane) * 128),
        (uint32_t)((warp_n * 64 + 32 + row_lane) * 128),
        (uint32_t)((warp_n * 64 + 48 + row_lane) * 128)};

    uint32_t afr[2][4][4];   // double-buffered fragments
    uint32_t bfr[2][4][4];

    for (int i = 0; i < NITER; i++) {
        CP_WAIT(STAGES - 2);
        __syncthreads();

        const uint32_t a_base = sA[i % STAGES];
        const uint32_t b_base = sB[i % STAGES];

        // fragment prefetch for ks = 0
        {
            uint32_t col = (uint32_t)((0 * 2 + kch_lane) * 16);
            #pragma unroll
            for (int mt = 0; mt < 4; mt++) ldsm_x4(afr[0][mt], a_base + SWZ128(a_row_off[mt] + col));
            #pragma unroll
            for (int nb = 0; nb < 4; nb++) ldsm_x4(bfr[0][nb], b_base + SWZ128(b_row_off[nb] + col));
        }

        // global prefetch for stage i+STAGES-1 (overlaps with MMA below)
        int ld = i + STAGES - 1;
        if (ld < NITER)
            load_stage(sA[ld % STAGES], sB[ld % STAGES], bm, bn, ld * BK, tid);
        CP_COMMIT();   // unconditional: keeps wait_group accounting exact in the tail

        #pragma unroll
        for (int ks = 0; ks < 4; ks++) {       // 4 x k16 per stage
            const int cur = ks & 1, nxt = cur ^ 1;
            if (ks < 3) {                       // prefetch fragments for ks+1
                uint32_t col = (uint32_t)(((ks + 1) * 2 + kch_lane) * 16);
                #pragma unroll
                for (int mt = 0; mt < 4; mt++) ldsm_x4(afr[nxt][mt], a_base + SWZ128(a_row_off[mt] + col));
                #pragma unroll
                for (int nb = 0; nb < 4; nb++) ldsm_x4(bfr[nxt][nb], b_base + SWZ128(b_row_off[nb] + col));
            }
            #pragma unroll
            for (int mt = 0; mt < 4; mt++)
                #pragma unroll
                for (int nt = 0; nt < 8; nt++)
                    mma16816(acc[mt][nt], afr[cur][mt],
                             bfr[cur][nt >> 1][nt & 1], bfr[cur][nt >> 1][(nt & 1) + 2]);
        }
    }

    // ---- epilogue: bias + direct fp32 stores (float2 per m16n8 fragment row) ----
    const int qrow = lane >> 2;          // 0..7
    const int qcol = 2 * (lane & 3);     // 0,2,4,6
    #pragma unroll
    for (int nt = 0; nt < 8; nt++) {
        int col = bn + warp_n * 64 + nt * 8 + qcol;
        float b0 = __ldg(bias + col);
        float b1 = __ldg(bias + col + 1);
        #pragma unroll
        for (int mt = 0; mt < 4; mt++) {
            int row = bm + warp_m * 64 + mt * 16 + qrow;
            float2 v0 = {acc[mt][nt][0] + b0, acc[mt][nt][1] + b1};
            float2 v1 = {acc[mt][nt][2] + b0, acc[mt][nt][3] + b1};
            *reinterpret_cast<float2*>(out + (size_t)row * N_DIM + col) = v0;
            *reinterpret_cast<float2*>(out + (size_t)(row + 8) * N_DIM + col) = v1;
        }
    }
}

// ---------------- launch ----------------
extern "C" void kernel_launch(void* const* d_in, const int* in_sizes, int n_in,
                              void* d_out, int out_size)
{
    const float* x      = (const float*)d_in[0];
    const int*   qw     = (const int*)  d_in[1];
    const float* scales = (const float*)d_in[2];
    const float* zeros  = (const float*)d_in[3];
    const float* bias   = (const float*)d_in[4];
    float* out          = (float*)d_out;

    cudaFuncSetAttribute(gemm_f16_kernel, cudaFuncAttributeMaxDynamicSharedMemorySize, SMEM_TOTAL);

    {
        size_t total = W_JOBS + X_JOBS;
        prologue_kernel<<<(unsigned)((total + 255) / 256), 256>>>(qw, scales, zeros, x);
    }
    {
        dim3 grid(N_DIM / BN, M_DIM / BM);   // (86, 32)
        gemm_f16_kernel<<<grid, THREADS, SMEM_TOTAL>>>(bias, out);
    }
}

// round 9
// speedup vs baseline: 1.0148x; 1.0148x over previous
#include <cuda_runtime.h>
#include <cuda_fp16.h>
#include <cstdint>

// GPTQ int4 linear on GB300 via legacy tensor path (mma.sync, base sm_103 target):
//   Pass 1 (fused): dequant qweight -> fp16 W[N,K]; convert x -> fp16.
//   Pass 2: 256x128x64 tiled fp16 GEMM, 512 threads (16 warps, warp tile 64x32),
//           mma.sync.m16n8k16 + ldmatrix, 3-stage cp.async pipeline.
// M=8192, N=11008, K=4096, GS=128.

#define M_DIM 8192
#define N_DIM 11008
#define K_DIM 4096
#define BM 256
#define BN 128
#define BK 64                 // halfs per stage (128 bytes per row, SW128)
#define STAGES 3
#define NITER (K_DIM / BK)    // 64
#define THREADS 512

__device__ __half g_Wh[(size_t)N_DIM * K_DIM];   // 90 MB
__device__ __half g_Xh[(size_t)M_DIM * K_DIM];   // 64 MB

#define SWZ128(o) ((o) ^ (((o) >> 3) & 0x70))

#define CP_ASYNC16(dst, src) \
    asm volatile("cp.async.cg.shared.global [%0], [%1], 16;" :: "r"(dst), "l"(src))
#define CP_COMMIT() asm volatile("cp.async.commit_group;" ::: "memory")
#define CP_WAIT(n)  asm volatile("cp.async.wait_group %0;" :: "n"(n) : "memory")

__device__ __forceinline__ uint32_t smem_u32(const void* p) {
    uint32_t a;
    asm("{ .reg .u64 t; cvta.to.shared.u64 t, %1; cvt.u32.u64 %0, t; }" : "=r"(a) : "l"(p));
    return a;
}
__device__ __forceinline__ void ldsm_x4(uint32_t* r, uint32_t addr) {
    asm volatile("ldmatrix.sync.aligned.m8n8.x4.shared.b16 {%0,%1,%2,%3}, [%4];"
                 : "=r"(r[0]), "=r"(r[1]), "=r"(r[2]), "=r"(r[3]) : "r"(addr));
}
__device__ __forceinline__ void mma16816(float* c, const uint32_t* a, uint32_t b0, uint32_t b1) {
    asm volatile("mma.sync.aligned.m16n8k16.row.col.f32.f16.f16.f32 "
                 "{%0,%1,%2,%3}, {%4,%5,%6,%7}, {%8,%9}, {%0,%1,%2,%3};"
                 : "+f"(c[0]), "+f"(c[1]), "+f"(c[2]), "+f"(c[3])
                 : "r"(a[0]), "r"(a[1]), "r"(a[2]), "r"(a[3]), "r"(b0), "r"(b1));
}

// ---------------- Pass 1 (fused): dequant W -> fp16 ; convert x -> fp16 ----------------
#define W_JOBS ((size_t)N_DIM * (K_DIM / 8))     // 5,636,096
#define X_JOBS ((size_t)M_DIM * (K_DIM / 8))     // 4,194,304

__global__ void prologue_kernel(const int* __restrict__ qw,        // [N, K/2], one byte per int32
                                const float* __restrict__ scales,  // [N, 32]
                                const float* __restrict__ zeros,   // [N, 32]
                                const float* __restrict__ x)       // [M, K]
{
    size_t t = (size_t)blockIdx.x * blockDim.x + threadIdx.x;
    if (t < W_JOBS) {
        int n  = (int)(t >> 9);           // K/8 = 512 per row
        int c4 = (int)(t & 511);
        int g  = c4 >> 4;                 // (c4*8)/128
        float sc = scales[(size_t)n * 32 + g];
        float zp = zeros [(size_t)n * 32 + g];
        int4 q = *reinterpret_cast<const int4*>(qw + (size_t)n * 2048 + c4 * 4);
        int qs[4] = {q.x, q.y, q.z, q.w};
        __half h[8];
        #pragma unroll
        for (int j = 0; j < 4; j++) {
            float lo = (float)(qs[j] & 15);
            float hi = (float)((qs[j] >> 4) & 15);
            h[2 * j    ] = __float2half_rn((lo - zp) * sc);
            h[2 * j + 1] = __float2half_rn((hi - zp) * sc);
        }
        *reinterpret_cast<uint4*>(&g_Wh[(size_t)n * K_DIM + (size_t)c4 * 8]) =
            *reinterpret_cast<const uint4*>(h);
    } else if (t - W_JOBS < X_JOBS) {
        size_t base = (t - W_JOBS) * 8;
        float4 a = *reinterpret_cast<const float4*>(x + base);
        float4 b = *reinterpret_cast<const float4*>(x + base + 4);
        __half h[8] = {__float2half_rn(a.x), __float2half_rn(a.y), __float2half_rn(a.z), __float2half_rn(a.w),
                       __float2half_rn(b.x), __float2half_rn(b.y), __float2half_rn(b.z), __float2half_rn(b.w)};
        *reinterpret_cast<uint4*>(&g_Xh[base]) = *reinterpret_cast<const uint4*>(h);
    }
}

// ---------------- Pass 2: mma.sync fp16 GEMM ----------------
// SMEM per stage: A 256x64 fp16 (32KB) + B 128x64 fp16 (16KB) = 48KB. 3 stages = 144KB.
#define A_BYTES 32768
#define STAGE_BYTES 49152
#define SMEM_TOTAL (STAGES * STAGE_BYTES)

__device__ __forceinline__ void load_stage(uint32_t sA, uint32_t sB,
                                           int bm, int bn, int k0, int tid)
{
    // A: 2048 16B-chunks -> 4 per thread. B: 1024 chunks -> 2 per thread.
    #pragma unroll
    for (int j = 0; j < 4; j++) {
        int chunk = tid + j * THREADS;
        int row = chunk >> 3, c16 = chunk & 7;
        uint32_t off = SWZ128((uint32_t)(row * 128 + c16 * 16));
        CP_ASYNC16(sA + off, g_Xh + (size_t)(bm + row) * K_DIM + k0 + c16 * 8);
    }
    #pragma unroll
    for (int j = 0; j < 2; j++) {
        int chunk = tid + j * THREADS;
        int row = chunk >> 3, c16 = chunk & 7;
        uint32_t off = SWZ128((uint32_t)(row * 128 + c16 * 16));
        CP_ASYNC16(sB + off, g_Wh + (size_t)(bn + row) * K_DIM + k0 + c16 * 8);
    }
}

__global__ __launch_bounds__(THREADS, 1)
void gemm_f16_kernel(const float* __restrict__ bias, float* __restrict__ out)
{
    extern __shared__ char smem[];
    const uint32_t sb = smem_u32(smem);
    const int tid = threadIdx.x;
    const int wid = tid >> 5, lane = tid & 31;
    const int warp_m = wid & 3;    // 0..3, 64 rows each
    const int warp_n = wid >> 2;   // 0..3, 32 cols each
    const int bn = blockIdx.x * BN;
    const int bm = blockIdx.y * BM;

    uint32_t sA[STAGES], sB[STAGES];
    #pragma unroll
    for (int s = 0; s < STAGES; s++) {
        sA[s] = sb + s * STAGE_BYTES;
        sB[s] = sA[s] + A_BYTES;
    }

    float acc[4][4][4];   // warp tile 64x32: [m16 tile][n8 tile][reg]
    #pragma unroll
    for (int a = 0; a < 4; a++)
        #pragma unroll
        for (int b = 0; b < 4; b++)
            #pragma unroll
            for (int c = 0; c < 4; c++)
                acc[a][b][c] = 0.0f;

    #pragma unroll
    for (int s = 0; s < STAGES - 1; s++) {
        load_stage(sA[s], sB[s], bm, bn, s * BK, tid);
        CP_COMMIT();
    }

    const int kch_lane = lane >> 4;        // 0/1: k-chunk selector within ldmatrix.x4
    const int row_lane = lane & 15;
    const uint32_t a_row_off[4] = {
        (uint32_t)((warp_m * 64 +  0 + row_lane) * 128),
        (uint32_t)((warp_m * 64 + 16 + row_lane) * 128),
        (uint32_t)((warp_m * 64 + 32 + row_lane) * 128),
        (uint32_t)((warp_m * 64 + 48 + row_lane) * 128)};
    const uint32_t b_row_off[2] = {
        (uint32_t)((warp_n * 32 +  0 + row_lane) * 128),
        (uint32_t)((warp_n * 32 + 16 + row_lane) * 128)};

    for (int i = 0; i < NITER; i++) {
        CP_WAIT(STAGES - 2);
        __syncthreads();

        // global prefetch for stage i+STAGES-1 (overlaps with MMAs below)
        int ld = i + STAGES - 1;
        if (ld < NITER)
            load_stage(sA[ld % STAGES], sB[ld % STAGES], bm, bn, ld * BK, tid);
        CP_COMMIT();   // unconditional: keeps wait_group accounting exact in the tail

        const uint32_t a_base = sA[i % STAGES];
        const uint32_t b_base = sB[i % STAGES];

        #pragma unroll
        for (int ks = 0; ks < 4; ks++) {       // 4 x k16 per stage
            const uint32_t col = (uint32_t)((ks * 2 + kch_lane) * 16);
            uint32_t afr[4][4];
            #pragma unroll
            for (int mt = 0; mt < 4; mt++)
                ldsm_x4(afr[mt], a_base + SWZ128(a_row_off[mt] + col));
            uint32_t bfr[2][4];
            #pragma unroll
            for (int nb = 0; nb < 2; nb++)
                ldsm_x4(bfr[nb], b_base + SWZ128(b_row_off[nb] + col));
            #pragma unroll
            for (int mt = 0; mt < 4; mt++)
                #pragma unroll
                for (int nt = 0; nt < 4; nt++)
                    mma16816(acc[mt][nt], afr[mt],
                             bfr[nt >> 1][nt & 1], bfr[nt >> 1][(nt & 1) + 2]);
        }
    }

    // ---- epilogue: bias + direct fp32 stores (float2 per m16n8 fragment row) ----
    const int qrow = lane >> 2;          // 0..7
    const int qcol = 2 * (lane & 3);     // 0,2,4,6
    #pragma unroll
    for (int nt = 0; nt < 4; nt++) {
        int col = bn + warp_n * 32 + nt * 8 + qcol;
        float b0 = __ldg(bias + col);
        float b1 = __ldg(bias + col + 1);
        #pragma unroll
        for (int mt = 0; mt < 4; mt++) {
            int row = bm + warp_m * 64 + mt * 16 + qrow;
            float2 v0 = {acc[mt][nt][0] + b0, acc[mt][nt][1] + b1};
            float2 v1 = {acc[mt][nt][2] + b0, acc[mt][nt][3] + b1};
            *reinterpret_cast<float2*>(out + (size_t)row * N_DIM + col) = v0;
            *reinterpret_cast<float2*>(out + (size_t)(row + 8) * N_DIM + col) = v1;
        }
    }
}

// ---------------- launch ----------------
extern "C" void kernel_launch(void* const* d_in, const int* in_sizes, int n_in,
                              void* d_out, int out_size)
{
    const float* x      = (const float*)d_in[0];
    const int*   qw     = (const int*)  d_in[1];
    const float* scales = (const float*)d_in[2];
    const float* zeros  = (const float*)d_in[3];
    const float* bias   = (const float*)d_in[4];
    float* out          = (float*)d_out;

    cudaFuncSetAttribute(gemm_f16_kernel, cudaFuncAttributeMaxDynamicSharedMemorySize, SMEM_TOTAL);

    {
        size_t total = W_JOBS + X_JOBS;
        prologue_kernel<<<(unsigned)((total + 255) / 256), 256>>>(qw, scales, zeros, x);
    }
    {
        dim3 grid(N_DIM / BN, M_DIM / BM);   // (86, 32)
        gemm_f16_kernel<<<grid, THREADS, SMEM_TOTAL>>>(bias, out);
    }
}

// round 10
// speedup vs baseline: 1.0939x; 1.0780x over previous
#include <cuda_runtime.h>
#include <cuda_fp16.h>
#include <cstdint>

// GPTQ int4 linear on GB300 via legacy tensor path (mma.sync, base sm_103 target):
//   Pass 1 (fused): dequant qweight -> fp16 W[N,K]; convert x -> fp16.
//   Pass 2: 128x128x64 tiled fp16 GEMM, 256 threads (8 warps, warp tile 64x32),
//           2 CTAs per SM (96KB smem each), mma.sync.m16n8k16 + ldmatrix,
//           3-stage cp.async pipeline.
// M=8192, N=11008, K=4096, GS=128.

#define M_DIM 8192
#define N_DIM 11008
#define K_DIM 4096
#define BM 128
#define BN 128
#define BK 64                 // halfs per stage (128 bytes per row, SW128)
#define STAGES 3
#define NITER (K_DIM / BK)    // 64
#define THREADS 256

__device__ __half g_Wh[(size_t)N_DIM * K_DIM];   // 90 MB
__device__ __half g_Xh[(size_t)M_DIM * K_DIM];   // 64 MB

#define SWZ128(o) ((o) ^ (((o) >> 3) & 0x70))

#define CP_ASYNC16(dst, src) \
    asm volatile("cp.async.cg.shared.global [%0], [%1], 16;" :: "r"(dst), "l"(src))
#define CP_COMMIT() asm volatile("cp.async.commit_group;" ::: "memory")
#define CP_WAIT(n)  asm volatile("cp.async.wait_group %0;" :: "n"(n) : "memory")

__device__ __forceinline__ uint32_t smem_u32(const void* p) {
    uint32_t a;
    asm("{ .reg .u64 t; cvta.to.shared.u64 t, %1; cvt.u32.u64 %0, t; }" : "=r"(a) : "l"(p));
    return a;
}
__device__ __forceinline__ void ldsm_x4(uint32_t* r, uint32_t addr) {
    asm volatile("ldmatrix.sync.aligned.m8n8.x4.shared.b16 {%0,%1,%2,%3}, [%4];"
                 : "=r"(r[0]), "=r"(r[1]), "=r"(r[2]), "=r"(r[3]) : "r"(addr));
}
__device__ __forceinline__ void mma16816(float* c, const uint32_t* a, uint32_t b0, uint32_t b1) {
    asm volatile("mma.sync.aligned.m16n8k16.row.col.f32.f16.f16.f32 "
                 "{%0,%1,%2,%3}, {%4,%5,%6,%7}, {%8,%9}, {%0,%1,%2,%3};"
                 : "+f"(c[0]), "+f"(c[1]), "+f"(c[2]), "+f"(c[3])
                 : "r"(a[0]), "r"(a[1]), "r"(a[2]), "r"(a[3]), "r"(b0), "r"(b1));
}

// ---------------- Pass 1 (fused): dequant W -> fp16 ; convert x -> fp16 ----------------
#define W_JOBS ((size_t)N_DIM * (K_DIM / 8))     // 5,636,096
#define X_JOBS ((size_t)M_DIM * (K_DIM / 8))     // 4,194,304

__global__ void prologue_kernel(const int* __restrict__ qw,        // [N, K/2], one byte per int32
                                const float* __restrict__ scales,  // [N, 32]
                                const float* __restrict__ zeros,   // [N, 32]
                                const float* __restrict__ x)       // [M, K]
{
    size_t t = (size_t)blockIdx.x * blockDim.x + threadIdx.x;
    if (t < W_JOBS) {
        int n  = (int)(t >> 9);           // K/8 = 512 per row
        int c4 = (int)(t & 511);
        int g  = c4 >> 4;                 // (c4*8)/128
        float sc = scales[(size_t)n * 32 + g];
        float zp = zeros [(size_t)n * 32 + g];
        int4 q = *reinterpret_cast<const int4*>(qw + (size_t)n * 2048 + c4 * 4);
        int qs[4] = {q.x, q.y, q.z, q.w};
        __half h[8];
        #pragma unroll
        for (int j = 0; j < 4; j++) {
            float lo = (float)(qs[j] & 15);
            float hi = (float)((qs[j] >> 4) & 15);
            h[2 * j    ] = __float2half_rn((lo - zp) * sc);
            h[2 * j + 1] = __float2half_rn((hi - zp) * sc);
        }
        *reinterpret_cast<uint4*>(&g_Wh[(size_t)n * K_DIM + (size_t)c4 * 8]) =
            *reinterpret_cast<const uint4*>(h);
    } else if (t - W_JOBS < X_JOBS) {
        size_t base = (t - W_JOBS) * 8;
        float4 a = *reinterpret_cast<const float4*>(x + base);
        float4 b = *reinterpret_cast<const float4*>(x + base + 4);
        __half h[8] = {__float2half_rn(a.x), __float2half_rn(a.y), __float2half_rn(a.z), __float2half_rn(a.w),
                       __float2half_rn(b.x), __float2half_rn(b.y), __float2half_rn(b.z), __float2half_rn(b.w)};
        *reinterpret_cast<uint4*>(&g_Xh[base]) = *reinterpret_cast<const uint4*>(h);
    }
}

// ---------------- Pass 2: mma.sync fp16 GEMM ----------------
// SMEM per stage: A 128x64 fp16 (16KB) + B 128x64 fp16 (16KB) = 32KB. 3 stages = 96KB.
// 2 CTAs co-resident per SM (192KB of 228KB).
#define A_BYTES 16384
#define STAGE_BYTES 32768
#define SMEM_TOTAL (STAGES * STAGE_BYTES)

__device__ __forceinline__ void load_stage(uint32_t sA, uint32_t sB,
                                           int bm, int bn, int k0, int tid)
{
    // A: 1024 16B-chunks -> 4 per thread. B: 1024 chunks -> 4 per thread.
    #pragma unroll
    for (int j = 0; j < 4; j++) {
        int chunk = tid + j * THREADS;
        int row = chunk >> 3, c16 = chunk & 7;
        uint32_t off = SWZ128((uint32_t)(row * 128 + c16 * 16));
        CP_ASYNC16(sA + off, g_Xh + (size_t)(bm + row) * K_DIM + k0 + c16 * 8);
    }
    #pragma unroll
    for (int j = 0; j < 4; j++) {
        int chunk = tid + j * THREADS;
        int row = chunk >> 3, c16 = chunk & 7;
        uint32_t off = SWZ128((uint32_t)(row * 128 + c16 * 16));
        CP_ASYNC16(sB + off, g_Wh + (size_t)(bn + row) * K_DIM + k0 + c16 * 8);
    }
}

__global__ __launch_bounds__(THREADS, 2)
void gemm_f16_kernel(const float* __restrict__ bias, float* __restrict__ out)
{
    extern __shared__ char smem[];
    const uint32_t sb = smem_u32(smem);
    const int tid = threadIdx.x;
    const int wid = tid >> 5, lane = tid & 31;
    const int warp_m = wid & 1;    // 0..1, 64 rows each
    const int warp_n = wid >> 1;   // 0..3, 32 cols each
    const int bn = blockIdx.x * BN;
    const int bm = blockIdx.y * BM;

    uint32_t sA[STAGES], sB[STAGES];
    #pragma unroll
    for (int s = 0; s < STAGES; s++) {
        sA[s] = sb + s * STAGE_BYTES;
        sB[s] = sA[s] + A_BYTES;
    }

    float acc[4][4][4];   // warp tile 64x32: [m16 tile][n8 tile][reg]
    #pragma unroll
    for (int a = 0; a < 4; a++)
        #pragma unroll
        for (int b = 0; b < 4; b++)
            #pragma unroll
            for (int c = 0; c < 4; c++)
                acc[a][b][c] = 0.0f;

    #pragma unroll
    for (int s = 0; s < STAGES - 1; s++) {
        load_stage(sA[s], sB[s], bm, bn, s * BK, tid);
        CP_COMMIT();
    }

    const int kch_lane = lane >> 4;        // 0/1: k-chunk selector within ldmatrix.x4
    const int row_lane = lane & 15;
    const uint32_t a_row_off[4] = {
        (uint32_t)((warp_m * 64 +  0 + row_lane) * 128),
        (uint32_t)((warp_m * 64 + 16 + row_lane) * 128),
        (uint32_t)((warp_m * 64 + 32 + row_lane) * 128),
        (uint32_t)((warp_m * 64 + 48 + row_lane) * 128)};
    const uint32_t b_row_off[2] = {
        (uint32_t)((warp_n * 32 +  0 + row_lane) * 128),
        (uint32_t)((warp_n * 32 + 16 + row_lane) * 128)};

    for (int i = 0; i < NITER; i++) {
        CP_WAIT(STAGES - 2);
        __syncthreads();

        // global prefetch for stage i+STAGES-1 (overlaps with MMAs below)
        int ld = i + STAGES - 1;
        if (ld < NITER)
            load_stage(sA[ld % STAGES], sB[ld % STAGES], bm, bn, ld * BK, tid);
        CP_COMMIT();   // unconditional: keeps wait_group accounting exact in the tail

        const uint32_t a_base = sA[i % STAGES];
        const uint32_t b_base = sB[i % STAGES];

        #pragma unroll
        for (int ks = 0; ks < 4; ks++) {       // 4 x k16 per stage
            const uint32_t col = (uint32_t)((ks * 2 + kch_lane) * 16);
            uint32_t afr[4][4];
            #pragma unroll
            for (int mt = 0; mt < 4; mt++)
                ldsm_x4(afr[mt], a_base + SWZ128(a_row_off[mt] + col));
            uint32_t bfr[2][4];
            #pragma unroll
            for (int nb = 0; nb < 2; nb++)
                ldsm_x4(bfr[nb], b_base + SWZ128(b_row_off[nb] + col));
            #pragma unroll
            for (int mt = 0; mt < 4; mt++)
                #pragma unroll
                for (int nt = 0; nt < 4; nt++)
                    mma16816(acc[mt][nt], afr[mt],
                             bfr[nt >> 1][nt & 1], bfr[nt >> 1][(nt & 1) + 2]);
        }
    }

    // ---- epilogue: bias + direct fp32 stores (float2 per m16n8 fragment row) ----
    const int qrow = lane >> 2;          // 0..7
    const int qcol = 2 * (lane & 3);     // 0,2,4,6
    #pragma unroll
    for (int nt = 0; nt < 4; nt++) {
        int col = bn + warp_n * 32 + nt * 8 + qcol;
        float b0 = __ldg(bias + col);
        float b1 = __ldg(bias + col + 1);
        #pragma unroll
        for (int mt = 0; mt < 4; mt++) {
            int row = bm + warp_m * 64 + mt * 16 + qrow;
            float2 v0 = {acc[mt][nt][0] + b0, acc[mt][nt][1] + b1};
            float2 v1 = {acc[mt][nt][2] + b0, acc[mt][nt][3] + b1};
            *reinterpret_cast<float2*>(out + (size_t)row * N_DIM + col) = v0;
            *reinterpret_cast<float2*>(out + (size_t)(row + 8) * N_DIM + col) = v1;
        }
    }
}

// ---------------- launch ----------------
extern "C" void kernel_launch(void* const* d_in, const int* in_sizes, int n_in,
                              void* d_out, int out_size)
{
    const float* x      = (const float*)d_in[0];
    const int*   qw     = (const int*)  d_in[1];
    const float* scales = (const float*)d_in[2];
    const float* zeros  = (const float*)d_in[3];
    const float* bias   = (const float*)d_in[4];
    float* out          = (float*)d_out;

    cudaFuncSetAttribute(gemm_f16_kernel, cudaFuncAttributeMaxDynamicSharedMemorySize, SMEM_TOTAL);

    {
        size_t total = W_JOBS + X_JOBS;
        prologue_kernel<<<(unsigned)((total + 255) / 256), 256>>>(qw, scales, zeros, x);
    }
    {
        dim3 grid(N_DIM / BN, M_DIM / BM);   // (86, 64)
        gemm_f16_kernel<<<grid, THREADS, SMEM_TOTAL>>>(bias, out);
    }
}

// round 11
// speedup vs baseline: 1.1784x; 1.0772x over previous
#include <cuda_runtime.h>
#include <cuda_fp16.h>
#include <cstdint>

// GPTQ int4 linear on GB300 via legacy tensor path (mma.sync, base sm_103 target):
//   Pass 1 (fused): dequant qweight -> fp16 W[N,K]; convert x -> fp16.
//   Pass 2: 128x128x64 tiled fp16 GEMM, 256 threads (8 warps, warp tile 64x32),
//           2 CTAs per SM, 3-stage cp.async pipeline with pointer-increment
//           addressing (no per-iter 64-bit address recompute).
// M=8192, N=11008, K=4096, GS=128.

#define M_DIM 8192
#define N_DIM 11008
#define K_DIM 4096
#define BM 128
#define BN 128
#define BK 64                 // halfs per stage (128 bytes per row, SW128)
#define STAGES 3
#define NITER (K_DIM / BK)    // 64
#define THREADS 256

__device__ __half g_Wh[(size_t)N_DIM * K_DIM];   // 90 MB
__device__ __half g_Xh[(size_t)M_DIM * K_DIM];   // 64 MB

#define SWZ128(o) ((o) ^ (((o) >> 3) & 0x70))

#define CP_ASYNC16(dst, src) \
    asm volatile("cp.async.cg.shared.global [%0], [%1], 16;" :: "r"(dst), "l"(src))
#define CP_COMMIT() asm volatile("cp.async.commit_group;" ::: "memory")
#define CP_WAIT(n)  asm volatile("cp.async.wait_group %0;" :: "n"(n) : "memory")

__device__ __forceinline__ uint32_t smem_u32(const void* p) {
    uint32_t a;
    asm("{ .reg .u64 t; cvta.to.shared.u64 t, %1; cvt.u32.u64 %0, t; }" : "=r"(a) : "l"(p));
    return a;
}
__device__ __forceinline__ void ldsm_x4(uint32_t* r, uint32_t addr) {
    asm volatile("ldmatrix.sync.aligned.m8n8.x4.shared.b16 {%0,%1,%2,%3}, [%4];"
                 : "=r"(r[0]), "=r"(r[1]), "=r"(r[2]), "=r"(r[3]) : "r"(addr));
}
__device__ __forceinline__ void mma16816(float* c, const uint32_t* a, uint32_t b0, uint32_t b1) {
    asm volatile("mma.sync.aligned.m16n8k16.row.col.f32.f16.f16.f32 "
                 "{%0,%1,%2,%3}, {%4,%5,%6,%7}, {%8,%9}, {%0,%1,%2,%3};"
                 : "+f"(c[0]), "+f"(c[1]), "+f"(c[2]), "+f"(c[3])
                 : "r"(a[0]), "r"(a[1]), "r"(a[2]), "r"(a[3]), "r"(b0), "r"(b1));
}

// ---------------- Pass 1 (fused): dequant W -> fp16 ; convert x -> fp16 ----------------
#define W_JOBS ((size_t)N_DIM * (K_DIM / 8))     // 5,636,096
#define X_JOBS ((size_t)M_DIM * (K_DIM / 8))     // 4,194,304

__global__ void prologue_kernel(const int* __restrict__ qw,        // [N, K/2], one byte per int32
                                const float* __restrict__ scales,  // [N, 32]
                                const float* __restrict__ zeros,   // [N, 32]
                                const float* __restrict__ x)       // [M, K]
{
    size_t t = (size_t)blockIdx.x * blockDim.x + threadIdx.x;
    if (t < W_JOBS) {
        int n  = (int)(t >> 9);           // K/8 = 512 per row
        int c4 = (int)(t & 511);
        int g  = c4 >> 4;                 // (c4*8)/128
        float sc = scales[(size_t)n * 32 + g];
        float zp = zeros [(size_t)n * 32 + g];
        int4 q = *reinterpret_cast<const int4*>(qw + (size_t)n * 2048 + c4 * 4);
        int qs[4] = {q.x, q.y, q.z, q.w};
        __half h[8];
        #pragma unroll
        for (int j = 0; j < 4; j++) {
            float lo = (float)(qs[j] & 15);
            float hi = (float)((qs[j] >> 4) & 15);
            h[2 * j    ] = __float2half_rn((lo - zp) * sc);
            h[2 * j + 1] = __float2half_rn((hi - zp) * sc);
        }
        *reinterpret_cast<uint4*>(&g_Wh[(size_t)n * K_DIM + (size_t)c4 * 8]) =
            *reinterpret_cast<const uint4*>(h);
    } else if (t - W_JOBS < X_JOBS) {
        size_t base = (t - W_JOBS) * 8;
        float4 a = *reinterpret_cast<const float4*>(x + base);
        float4 b = *reinterpret_cast<const float4*>(x + base + 4);
        __half h[8] = {__float2half_rn(a.x), __float2half_rn(a.y), __float2half_rn(a.z), __float2half_rn(a.w),
                       __float2half_rn(b.x), __float2half_rn(b.y), __float2half_rn(b.z), __float2half_rn(b.w)};
        *reinterpret_cast<uint4*>(&g_Xh[base]) = *reinterpret_cast<const uint4*>(h);
    }
}

// ---------------- Pass 2: mma.sync fp16 GEMM ----------------
// SMEM per stage: A 128x64 fp16 (16KB) + B 128x64 fp16 (16KB) = 32KB. 3 stages = 96KB.
// 2 CTAs co-resident per SM (192KB of 228KB).
#define A_BYTES 16384
#define STAGE_BYTES 32768
#define SMEM_TOTAL (STAGES * STAGE_BYTES)

__global__ __launch_bounds__(THREADS, 2)
void gemm_f16_kernel(const float* __restrict__ bias, float* __restrict__ out)
{
    extern __shared__ char smem[];
    const uint32_t sb = smem_u32(smem);
    const int tid = threadIdx.x;
    const int wid = tid >> 5, lane = tid & 31;
    const int warp_m = wid & 1;    // 0..1, 64 rows each
    const int warp_n = wid >> 1;   // 0..3, 32 cols each
    const int bn = blockIdx.x * BN;
    const int bm = blockIdx.y * BM;

    uint32_t sA[STAGES], sB[STAGES];
    #pragma unroll
    for (int s = 0; s < STAGES; s++) {
        sA[s] = sb + s * STAGE_BYTES;
        sB[s] = sA[s] + A_BYTES;
    }

    // ---- precomputed cp.async addressing: 8 global ptrs + 4 smem dst offsets ----
    // chunk map identical for A and B (1024 16B-chunks, 4 per thread).
    const __half* ap[4];
    const __half* bp[4];
    uint32_t dst[4];
    #pragma unroll
    for (int j = 0; j < 4; j++) {
        int chunk = tid + j * THREADS;
        int row = chunk >> 3, c16 = chunk & 7;
        dst[j] = SWZ128((uint32_t)(row * 128 + c16 * 16));
        ap[j] = g_Xh + (size_t)(bm + row) * K_DIM + c16 * 8;
        bp[j] = g_Wh + (size_t)(bn + row) * K_DIM + c16 * 8;
    }

    float acc[4][4][4];   // warp tile 64x32: [m16 tile][n8 tile][reg]
    #pragma unroll
    for (int a = 0; a < 4; a++)
        #pragma unroll
        for (int b = 0; b < 4; b++)
            #pragma unroll
            for (int c = 0; c < 4; c++)
                acc[a][b][c] = 0.0f;

    // prologue: fill stages 0..STAGES-2
    #pragma unroll
    for (int s = 0; s < STAGES - 1; s++) {
        #pragma unroll
        for (int j = 0; j < 4; j++) CP_ASYNC16(sA[s] + dst[j], ap[j]);
        #pragma unroll
        for (int j = 0; j < 4; j++) CP_ASYNC16(sB[s] + dst[j], bp[j]);
        #pragma unroll
        for (int j = 0; j < 4; j++) { ap[j] += BK; bp[j] += BK; }
        CP_COMMIT();
    }

    const int kch_lane = lane >> 4;        // 0/1: k-chunk selector within ldmatrix.x4
    const int row_lane = lane & 15;
    const uint32_t a_row_off[4] = {
        (uint32_t)((warp_m * 64 +  0 + row_lane) * 128),
        (uint32_t)((warp_m * 64 + 16 + row_lane) * 128),
        (uint32_t)((warp_m * 64 + 32 + row_lane) * 128),
        (uint32_t)((warp_m * 64 + 48 + row_lane) * 128)};
    const uint32_t b_row_off[2] = {
        (uint32_t)((warp_n * 32 +  0 + row_lane) * 128),
        (uint32_t)((warp_n * 32 + 16 + row_lane) * 128)};

    int st = 0;                  // stage consumed this iter
    int ls = STAGES - 1;         // stage filled this iter

    for (int i = 0; i < NITER; i++) {
        CP_WAIT(STAGES - 2);
        __syncthreads();

        // global prefetch for stage i+STAGES-1 (overlaps with MMAs below)
        if (i + STAGES - 1 < NITER) {
            #pragma unroll
            for (int j = 0; j < 4; j++) CP_ASYNC16(sA[ls] + dst[j], ap[j]);
            #pragma unroll
            for (int j = 0; j < 4; j++) CP_ASYNC16(sB[ls] + dst[j], bp[j]);
            #pragma unroll
            for (int j = 0; j < 4; j++) { ap[j] += BK; bp[j] += BK; }
        }
        CP_COMMIT();   // unconditional: keeps wait_group accounting exact in the tail

        const uint32_t a_base = sA[st];
        const uint32_t b_base = sB[st];

        #pragma unroll
        for (int ks = 0; ks < 4; ks++) {       // 4 x k16 per stage
            const uint32_t col = (uint32_t)((ks * 2 + kch_lane) * 16);
            uint32_t afr[4][4];
            uint32_t bfr[2][4];
            // order: A0, B0, B1, then A1..A3 — first MMA's operands land earliest
            ldsm_x4(afr[0], a_base + SWZ128(a_row_off[0] + col));
            ldsm_x4(bfr[0], b_base + SWZ128(b_row_off[0] + col));
            ldsm_x4(bfr[1], b_base + SWZ128(b_row_off[1] + col));
            ldsm_x4(afr[1], a_base + SWZ128(a_row_off[1] + col));
            ldsm_x4(afr[2], a_base + SWZ128(a_row_off[2] + col));
            ldsm_x4(afr[3], a_base + SWZ128(a_row_off[3] + col));
            #pragma unroll
            for (int mt = 0; mt < 4; mt++)
                #pragma unroll
                for (int nt = 0; nt < 4; nt++)
                    mma16816(acc[mt][nt], afr[mt],
                             bfr[nt >> 1][nt & 1], bfr[nt >> 1][(nt & 1) + 2]);
        }

        if (++st == STAGES) st = 0;
        if (++ls == STAGES) ls = 0;
    }

    // ---- epilogue: bias + direct fp32 stores (float2 per m16n8 fragment row) ----
    const int qrow = lane >> 2;          // 0..7
    const int qcol = 2 * (lane & 3);     // 0,2,4,6
    #pragma unroll
    for (int nt = 0; nt < 4; nt++) {
        int col = bn + warp_n * 32 + nt * 8 + qcol;
        float b0 = __ldg(bias + col);
        float b1 = __ldg(bias + col + 1);
        #pragma unroll
        for (int mt = 0; mt < 4; mt++) {
            int row = bm + warp_m * 64 + mt * 16 + qrow;
            float2 v0 = {acc[mt][nt][0] + b0, acc[mt][nt][1] + b1};
            float2 v1 = {acc[mt][nt][2] + b0, acc[mt][nt][3] + b1};
            *reinterpret_cast<float2*>(out + (size_t)row * N_DIM + col) = v0;
            *reinterpret_cast<float2*>(out + (size_t)(row + 8) * N_DIM + col) = v1;
        }
    }
}

// ---------------- launch ----------------
extern "C" void kernel_launch(void* const* d_in, const int* in_sizes, int n_in,
                              void* d_out, int out_size)
{
    const float* x      = (const float*)d_in[0];
    const int*   qw     = (const int*)  d_in[1];
    const float* scales = (const float*)d_in[2];
    const float* zeros  = (const float*)d_in[3];
    const float* bias   = (const float*)d_in[4];
    float* out          = (float*)d_out;

    cudaFuncSetAttribute(gemm_f16_kernel, cudaFuncAttributeMaxDynamicSharedMemorySize, SMEM_TOTAL);

    {
        size_t total = W_JOBS + X_JOBS;
        prologue_kernel<<<(unsigned)((total + 255) / 256), 256>>>(qw, scales, zeros, x);
    }
    {
        dim3 grid(N_DIM / BN, M_DIM / BM);   // (86, 64)
        gemm_f16_kernel<<<grid, THREADS, SMEM_TOTAL>>>(bias, out);
    }
}